// round 1
// baseline (speedup 1.0000x reference)
#include <cuda_runtime.h>
#include <math.h>

// SoftNCutsLoss: N=2, K=4, C=1, S=8000.
// out[n] = K - sum_k num_k/(den_k+1e-8)
//   num_k = sum_ij a_k[i] w[i,j] a_k[j],  den_k = sum_ij a_k[i] w[i,j]
//   w[i,j] = exp(-(x_i - x_j)^2)   (C=1, sigma=1)
//
// Histogram method: bin x into B bins; per bin keep moments (S,T,U) of each of
// 5 channels {ones, a0..a3}. 2nd-order Taylor of f(d)=exp(-d^2) around
// bin-center distances reduces the O(S^2) pair sum to O(B^2) bin pairs with a
// (2B-1)-entry exp table. Residual O(delta^3) ~ 2e-5 relative.

#define NB 512
#define NCH 5
#define HALF_RANGE 8.0f
#define DELTA (2.0f * HALF_RANGE / (float)NB)
#define QCH 8                    // q-chunks per p-row
#define QLEN (NB / QCH)          // 64
#define BPN ((NB * QCH) / 256)   // 16 blocks per batch item

// scratch (allocation-free rule: __device__ globals)
__device__ float4 g_hist[2][NB][NCH];   // per (n,bin,channel): {S, T, U, pad}
__device__ float  g_acc[2][8];          // [n][0..3]=num_k, [n][4..7]=den_k

__global__ void zero_kernel() {
    int g = blockIdx.x * blockDim.x + threadIdx.x;
    float* h = (float*)g_hist;
    const int nh = 2 * NB * NCH * 4;
    if (g < nh) h[g] = 0.0f;
    if (g < 16) ((float*)g_acc)[g] = 0.0f;
}

__global__ void hist_kernel(const float* __restrict__ labels,
                            const float* __restrict__ inputs, int S) {
    int g = blockIdx.x * blockDim.x + threadIdx.x;
    if (g >= 2 * S) return;
    int n = g / S;
    int i = g - n * S;
    float x = inputs[n * S + i];
    int b = (int)floorf((x + HALF_RANGE) * (1.0f / DELTA));
    b = max(0, min(NB - 1, b));
    float c = -HALF_RANGE + ((float)b + 0.5f) * DELTA;
    float xi = x - c;
    float xi2 = xi * xi;
    float4* h = &g_hist[n][b][0];
    atomicAdd(&h[0].x, 1.0f);
    atomicAdd(&h[0].y, xi);
    atomicAdd(&h[0].z, xi2);
#pragma unroll
    for (int k = 0; k < 4; k++) {
        float a = labels[(n * 4 + k) * S + i];
        atomicAdd(&h[k + 1].x, a);
        atomicAdd(&h[k + 1].y, a * xi);
        atomicAdd(&h[k + 1].z, a * xi2);
    }
}

__global__ __launch_bounds__(256) void pair_kernel() {
    __shared__ float4 sh[NB * NCH];     // 40 KB histogram (one n)
    __shared__ float  shf[2 * NB - 1];  // exp table over distinct bin distances
    __shared__ float  red[8][8];        // per-warp partials

    int tid = threadIdx.x;
    int n = blockIdx.x / BPN;
    int sub = blockIdx.x % BPN;

    const float4* gh = &g_hist[n][0][0];
    for (int i = tid; i < NB * NCH; i += 256) sh[i] = gh[i];
    for (int i = tid; i < 2 * NB - 1; i += 256) {
        float d = (float)(i - (NB - 1)) * DELTA;
        shf[i] = expf(-d * d);
    }
    __syncthreads();

    // task mapping: warp lanes share q-chunk, consecutive p (conflict-free table)
    int t = sub * 256 + tid;
    int p = t % NB;
    int qc = t / NB;
    int q0 = qc * QLEN;

    float accP[NCH], accQ[NCH], accR[NCH];
#pragma unroll
    for (int c = 0; c < NCH; c++) { accP[c] = 0.f; accQ[c] = 0.f; accR[c] = 0.f; }

#pragma unroll 4
    for (int q = q0; q < q0 + QLEN; q++) {
        float f = shf[p - q + (NB - 1)];
        float d = (float)(p - q) * DELTA;
        float fp = -2.0f * d * f;                 // f'
        float fh = (2.0f * d * d - 1.0f) * f;     // f''/2
#pragma unroll
        for (int c = 0; c < NCH; c++) {
            float4 h = sh[q * NCH + c];           // broadcast across the warp
            accP[c] = fmaf(f, h.x, fmaf(-fp, h.y, fmaf(fh, h.z, accP[c])));
            accQ[c] = fmaf(fp, h.x, fmaf(-2.0f * fh, h.y, accQ[c]));
            accR[c] = fmaf(fh, h.x, accR[c]);
        }
    }

    // combine with this p-row's own moments
    float vals[8];
#pragma unroll
    for (int k = 0; k < 4; k++) {
        float4 pa = sh[p * NCH + (k + 1)];
        vals[k]     = pa.x * accP[k + 1] + pa.y * accQ[k + 1] + pa.z * accR[k + 1]; // num_k
        vals[4 + k] = pa.x * accP[0]     + pa.y * accQ[0]     + pa.z * accR[0];     // den_k
    }

    // warp reduce
#pragma unroll
    for (int v = 0; v < 8; v++)
#pragma unroll
        for (int off = 16; off; off >>= 1)
            vals[v] += __shfl_xor_sync(0xffffffffu, vals[v], off);

    int warp = tid >> 5, lane = tid & 31;
    if (lane == 0)
#pragma unroll
        for (int v = 0; v < 8; v++) red[warp][v] = vals[v];
    __syncthreads();

    if (tid < 8) {
        float s = 0.f;
#pragma unroll
        for (int w = 0; w < 8; w++) s += red[w][tid];
        atomicAdd(&g_acc[n][tid], s);
    }
}

__global__ void final_kernel(float* __restrict__ out) {
    int n = threadIdx.x;
    if (n < 2) {
        float s = 0.0f;
#pragma unroll
        for (int k = 0; k < 4; k++)
            s += g_acc[n][k] / (g_acc[n][4 + k] + 1e-8f);
        out[n] = 4.0f - s;
    }
}

extern "C" void kernel_launch(void* const* d_in, const int* in_sizes, int n_in,
                              void* d_out, int out_size) {
    const float* labels = (const float*)d_in[0];  // (2,4,S)
    const float* inputs = (const float*)d_in[1];  // (2,1,S)
    int S = in_sizes[1] / 2;

    zero_kernel<<<(2 * NB * NCH * 4 + 255) / 256, 256>>>();
    hist_kernel<<<(2 * S + 255) / 256, 256>>>(labels, inputs, S);
    pair_kernel<<<2 * BPN, 256>>>();
    final_kernel<<<1, 32>>>((float*)d_out);
}